// round 10
// baseline (speedup 1.0000x reference)
#include <cuda_runtime.h>
#include <cstdint>

#define E_NUM   500000
#define H_DIM   256
#define PAIRS   (E_NUM / 2)      // 250000
#define BN_EPS  1e-5f
#define GRID    444              // 148 SMs x 3 co-resident blocks
#define PER1    565              // ceil(250000/443) stats pairs/block
#define NTILES  31250            // E/16 edge tiles for tensor phase 2
#define NWARPS  (GRID * 8)       // 3552 warps

typedef unsigned long long u64;

// -------- device scratch (static, no allocation) --------
__device__ float g_sum[H_DIM];                     // zero-init
__device__ float g_sumsq[H_DIM];
__device__ __align__(16) float g_ncf[(size_t)E_NUM * 8];  // plain nc [E,8], 16MB
__device__ float g_Craw[H_DIM * 8];                // W2@Wv@Wo@Wp
__device__ float g_biaspart[8];                    // b2@P2 + bv@P1 + bo@Wp + bp
__device__ unsigned g_arrive = 0;
__device__ volatile unsigned g_release = 0;
__device__ unsigned g_finish = 0;

// -------- f32x2 helpers (phase 1) --------
__device__ __forceinline__ u64 pack2(float lo, float hi) {
    u64 r;
    asm("mov.b64 %0, {%1, %2};" : "=l"(r)
        : "r"(__float_as_uint(lo)), "r"(__float_as_uint(hi)));
    return r;
}
__device__ __forceinline__ void unpack2(u64 v, float &lo, float &hi) {
    unsigned int a, b;
    asm("mov.b64 {%0, %1}, %2;" : "=r"(a), "=r"(b) : "l"(v));
    lo = __uint_as_float(a); hi = __uint_as_float(b);
}
__device__ __forceinline__ u64 fma2(u64 a, u64 b, u64 c) {
    u64 d;
    asm("fma.rn.f32x2 %0, %1, %2, %3;" : "=l"(d) : "l"(a), "l"(b), "l"(c));
    return d;
}
__device__ __forceinline__ u64 add2(u64 a, u64 b) {
    u64 d;
    asm("add.rn.f32x2 %0, %1, %2;" : "=l"(d) : "l"(a), "l"(b));
    return d;
}
__device__ __forceinline__ u64 relu2(u64 h) {
    float lo, hi; unpack2(h, lo, hi);
    return pack2(fmaxf(lo, 0.f), fmaxf(hi, 0.f));
}
__device__ __forceinline__ float wred(float v) {
    v += __shfl_down_sync(0xffffffffu, v, 16);
    v += __shfl_down_sync(0xffffffffu, v, 8);
    v += __shfl_down_sync(0xffffffffu, v, 4);
    v += __shfl_down_sync(0xffffffffu, v, 2);
    v += __shfl_down_sync(0xffffffffu, v, 1);
    return v;
}

// -------- tf32 mma helpers (phase 2) --------
__device__ __forceinline__ unsigned tf32r(float x) {
    unsigned u;
    asm("cvt.rna.tf32.f32 %0, %1;" : "=r"(u) : "f"(x));
    return u;
}
__device__ __forceinline__ void mma_init(float &d0, float &d1, float &d2, float &d3,
    unsigned a0, unsigned a1, unsigned a2, unsigned a3,
    unsigned b0, unsigned b1,
    float c0, float c1, float c2, float c3) {
    asm("mma.sync.aligned.m16n8k8.row.col.f32.tf32.tf32.f32 "
        "{%0,%1,%2,%3}, {%4,%5,%6,%7}, {%8,%9}, {%10,%11,%12,%13};"
        : "=f"(d0), "=f"(d1), "=f"(d2), "=f"(d3)
        : "r"(a0), "r"(a1), "r"(a2), "r"(a3), "r"(b0), "r"(b1),
          "f"(c0), "f"(c1), "f"(c2), "f"(c3));
}
__device__ __forceinline__ void mma_acc(float &c0, float &c1, float &c2, float &c3,
    unsigned a0, unsigned a1, unsigned a2, unsigned a3,
    unsigned b0, unsigned b1) {
    asm("mma.sync.aligned.m16n8k8.row.col.f32.tf32.tf32.f32 "
        "{%0,%1,%2,%3}, {%4,%5,%6,%7}, {%8,%9}, {%0,%1,%2,%3};"
        : "+f"(c0), "+f"(c1), "+f"(c2), "+f"(c3)
        : "r"(a0), "r"(a1), "r"(a2), "r"(a3), "r"(b0), "r"(b1));
}

__global__ void __launch_bounds__(256, 3)
fused(const float* __restrict__ ea, const float* __restrict__ nf,
      const int*   __restrict__ eidx,
      const float* __restrict__ W1, const float* __restrict__ b1,
      const float* __restrict__ gamma, const float* __restrict__ beta,
      const float* __restrict__ W2, const float* __restrict__ b2,
      const float* __restrict__ Wv, const float* __restrict__ bv,
      const float* __restrict__ Wo, const float* __restrict__ bo,
      const float* __restrict__ Wp, const float* __restrict__ bp,
      float* __restrict__ out)
{
    __shared__ __align__(16) unsigned char s_buf[18432];
    __shared__ __align__(16) u64 w1s[H_DIM * 8];   // W1^T duplicated (phase 1)
    __shared__ u64 b1s[H_DIM];
    __shared__ float dhf[8];
    __shared__ float a_s[H_DIM], c_s[H_DIM];

    const int t = threadIdx.x;
    const int b = blockIdx.x;
    const int lane = t & 31, warp = t >> 5;

    #pragma unroll
    for (int d = 0; d < 8; d++) {
        float v = W1[d * H_DIM + t];
        w1s[t * 8 + d] = pack2(v, v);
    }
    { float bb = b1[t]; b1s[t] = pack2(bb, bb); }

    if (b == 0) {
        // ============ weight chain (overlaps the stats pass) ============
        float* bufA = (float*)s_buf;
        float* bufB = bufA + 2304;
        for (int i = t; i < H_DIM * 8; i += 256)
            bufA[(i >> 3) * 9 + (i & 7)] = Wp[i];
        __syncthreads();
        float biask = 0.f;
        for (int j = lane; j < H_DIM; j += 32) biask += bo[j] * bufA[j * 9 + warp];
        for (int jj = warp; jj < H_DIM; jj += 8) {
            float a0=0,a1=0,a2=0,a3=0,a4=0,a5=0,a6=0,a7=0;
            #pragma unroll
            for (int qb = 0; qb < 8; qb++) {
                int q = qb * 32 + lane;
                float av = Wo[jj * H_DIM + q];
                const float* ir = bufA + q * 9;
                a0 += av*ir[0]; a1 += av*ir[1]; a2 += av*ir[2]; a3 += av*ir[3];
                a4 += av*ir[4]; a5 += av*ir[5]; a6 += av*ir[6]; a7 += av*ir[7];
            }
            a0=wred(a0); a1=wred(a1); a2=wred(a2); a3=wred(a3);
            a4=wred(a4); a5=wred(a5); a6=wred(a6); a7=wred(a7);
            if (lane == 0) {
                float* orow = bufB + jj * 9;
                orow[0]=a0; orow[1]=a1; orow[2]=a2; orow[3]=a3;
                orow[4]=a4; orow[5]=a5; orow[6]=a6; orow[7]=a7;
            }
        }
        __syncthreads();
        for (int j = lane; j < H_DIM; j += 32) biask += bv[j] * bufB[j * 9 + warp];
        for (int jj = warp; jj < H_DIM; jj += 8) {
            float a0=0,a1=0,a2=0,a3=0,a4=0,a5=0,a6=0,a7=0;
            #pragma unroll
            for (int qb = 0; qb < 8; qb++) {
                int q = qb * 32 + lane;
                float av = Wv[jj * H_DIM + q];
                const float* ir = bufB + q * 9;
                a0 += av*ir[0]; a1 += av*ir[1]; a2 += av*ir[2]; a3 += av*ir[3];
                a4 += av*ir[4]; a5 += av*ir[5]; a6 += av*ir[6]; a7 += av*ir[7];
            }
            a0=wred(a0); a1=wred(a1); a2=wred(a2); a3=wred(a3);
            a4=wred(a4); a5=wred(a5); a6=wred(a6); a7=wred(a7);
            if (lane == 0) {
                float* orow = bufA + jj * 9;
                orow[0]=a0; orow[1]=a1; orow[2]=a2; orow[3]=a3;
                orow[4]=a4; orow[5]=a5; orow[6]=a6; orow[7]=a7;
            }
        }
        __syncthreads();
        for (int j = lane; j < H_DIM; j += 32) biask += b2[j] * bufA[j * 9 + warp];
        for (int jj = warp; jj < H_DIM; jj += 8) {
            float a0=0,a1=0,a2=0,a3=0,a4=0,a5=0,a6=0,a7=0;
            #pragma unroll
            for (int qb = 0; qb < 8; qb++) {
                int q = qb * 32 + lane;
                float av = W2[jj * H_DIM + q];
                const float* ir = bufA + q * 9;
                a0 += av*ir[0]; a1 += av*ir[1]; a2 += av*ir[2]; a3 += av*ir[3];
                a4 += av*ir[4]; a5 += av*ir[5]; a6 += av*ir[6]; a7 += av*ir[7];
            }
            a0=wred(a0); a1=wred(a1); a2=wred(a2); a3=wred(a3);
            a4=wred(a4); a5=wred(a5); a6=wred(a6); a7=wred(a7);
            if (lane == 0) {
                float* orow = g_Craw + jj * 8;
                orow[0]=a0; orow[1]=a1; orow[2]=a2; orow[3]=a3;
                orow[4]=a4; orow[5]=a5; orow[6]=a6; orow[7]=a7;
            }
        }
        biask = wred(biask);
        if (lane == 0) g_biaspart[warp] = biask + bp[warp];
    } else {
        // ============ phase 1: gather + cache nc + relu stats ============
        int s1 = (b - 1) * PER1;
        int e1 = s1 + PER1; if (e1 > PAIRS) e1 = PAIRS;
        u64* ncs = (u64*)s_buf;
        const float4* nf4 = (const float4*)nf;

        const ulonglong2* wd = (const ulonglong2*)&w1s[t * 8];
        ulonglong2 w01 = wd[0], w23 = wd[1], w45 = wd[2], w67 = wd[3];
        u64 bdup = b1s[t];
        u64 sum2 = 0ull, sq2 = 0ull;

        for (int base = s1; base < e1; base += 256) {
            int cnt = e1 - base; if (cnt > 256) cnt = 256;
            __syncthreads();
            if (t < cnt) {
                int p  = base + t;
                int e0 = 2 * p;
                int sA = eidx[e0],         sB = eidx[e0 + 1];
                int dA = eidx[E_NUM + e0], dB = eidx[E_NUM + e0 + 1];
                float4 sa0 = nf4[2*sA], sa1 = nf4[2*sA+1];
                float4 da0 = nf4[2*dA], da1 = nf4[2*dA+1];
                float4 sb0 = nf4[2*sB], sb1 = nf4[2*sB+1];
                float4 db0 = nf4[2*dB], db1 = nf4[2*dB+1];
                float l0 = 0.5f*(sa0.x+da0.x), h0 = 0.5f*(sb0.x+db0.x);
                float l1 = 0.5f*(sa0.y+da0.y), h1 = 0.5f*(sb0.y+db0.y);
                float l2 = 0.5f*(sa0.z+da0.z), h2 = 0.5f*(sb0.z+db0.z);
                float l3 = 0.5f*(sa0.w+da0.w), h3 = 0.5f*(sb0.w+db0.w);
                float l4 = 0.5f*(sa1.x+da1.x), h4 = 0.5f*(sb1.x+db1.x);
                float l5 = 0.5f*(sa1.y+da1.y), h5 = 0.5f*(sb1.y+db1.y);
                float l6 = 0.5f*(sa1.z+da1.z), h6 = 0.5f*(sb1.z+db1.z);
                float l7 = 0.5f*(sa1.w+da1.w), h7 = 0.5f*(sb1.w+db1.w);
                u64 ncp[8];
                ncp[0] = pack2(l0, h0); ncp[1] = pack2(l1, h1);
                ncp[2] = pack2(l2, h2); ncp[3] = pack2(l3, h3);
                ncp[4] = pack2(l4, h4); ncp[5] = pack2(l5, h5);
                ncp[6] = pack2(l6, h6); ncp[7] = pack2(l7, h7);
                #pragma unroll
                for (int d = 0; d < 8; d++) ncs[t * 8 + d] = ncp[d];
                float4* nr = (float4*)(g_ncf + (size_t)(2 * p) * 8);
                nr[0] = make_float4(l0, l1, l2, l3);
                nr[1] = make_float4(l4, l5, l6, l7);
                nr[2] = make_float4(h0, h1, h2, h3);
                nr[3] = make_float4(h4, h5, h6, h7);
            }
            __syncthreads();
            for (int e2 = 0; e2 < cnt; e2++) {
                const ulonglong2* c = (const ulonglong2*)&ncs[e2 * 8];
                ulonglong2 c01 = c[0], c23 = c[1], c45 = c[2], c67 = c[3];
                u64 h = bdup;
                h = fma2(c01.x, w01.x, h); h = fma2(c01.y, w01.y, h);
                h = fma2(c23.x, w23.x, h); h = fma2(c23.y, w23.y, h);
                h = fma2(c45.x, w45.x, h); h = fma2(c45.y, w45.y, h);
                h = fma2(c67.x, w67.x, h); h = fma2(c67.y, w67.y, h);
                h = relu2(h);
                sum2 = add2(sum2, h);
                sq2  = fma2(h, h, sq2);
            }
        }
        float slo, shi, qlo, qhi;
        unpack2(sum2, slo, shi);
        unpack2(sq2, qlo, qhi);
        atomicAdd(&g_sum[t],   slo + shi);
        atomicAdd(&g_sumsq[t], qlo + qhi);
    }

    // ============ grid barrier ============
    __syncthreads();
    if (t == 0) {
        __threadfence();
        if (atomicAdd(&g_arrive, 1) == GRID - 1) {
            g_release = 1;
        } else {
            while (g_release == 0) { }
        }
        __threadfence();
    }
    __syncthreads();

    // ============ finalize BN, dh, fragment tables (per block) ============
    {
        const float invE = 1.f / (float)E_NUM;
        float mu  = g_sum[t] * invE;
        float var = g_sumsq[t] * invE - mu * mu;
        float aj  = gamma[t] * rsqrtf(var + BN_EPS);
        a_s[t] = aj;
        c_s[t] = beta[t] - mu * aj;
    }
    __syncthreads();
    {
        float acc = 0.f;
        for (int j = lane; j < H_DIM; j += 32) acc += c_s[j] * g_Craw[j * 8 + warp];
        acc = wred(acc);
        if (lane == 0) dhf[warp] = 0.5f * (acc + g_biaspart[warp]);
    }
    // fragment tables (tf32-preconverted)
    float2* w1f = (float2*)s_buf;                    // [1024] GEMM1 B frags
    float2* mf  = (float2*)(s_buf + 8192);           // [1024] GEMM2 B frags (tau-permuted rows)
    float2* b1f = (float2*)(s_buf + 16384);          // [128]  b1 col pairs
    for (int i = t; i < 1024; i += 256) {
        int q = i >> 5, l = i & 31;
        int kk = l & 3, nn = l >> 2;
        float w0 = W1[kk * H_DIM + q * 8 + nn];
        float w1v = W1[(kk + 4) * H_DIM + q * 8 + nn];
        w1f[i] = make_float2(__uint_as_float(tf32r(w0)), __uint_as_float(tf32r(w1v)));
        // GEMM2 B rows permuted: K slot kk -> j = q*8 + 2*kk; slot kk+4 -> j = q*8 + 2*kk+1
        int j0 = q * 8 + 2 * kk;
        float m0 = 0.5f * a_s[j0] * g_Craw[j0 * 8 + nn];
        float m1 = 0.5f * a_s[j0 + 1] * g_Craw[(j0 + 1) * 8 + nn];
        mf[i] = make_float2(__uint_as_float(tf32r(m0)), __uint_as_float(tf32r(m1)));
    }
    for (int i = t; i < 128; i += 256) {
        int q = i >> 2, q4 = i & 3;
        b1f[i] = make_float2(b1[q * 8 + 2 * q4], b1[q * 8 + 2 * q4 + 1]);
    }
    __syncthreads();

    // ============ phase 2: tensor contraction, 1 tile/warp iter (reg-lean) ===
    {
        const int warp_gid = b * 8 + warp;
        const int g = lane >> 2, q4 = lane & 3;
        const float dh0 = dhf[2 * q4], dh1 = dhf[2 * q4 + 1];

        for (int tau = warp_gid; tau < NTILES; tau += NWARPS) {
            int pe = tau << 4;
            const float* r0 = g_ncf + (size_t)(pe + g) * 8;
            unsigned a0 = tf32r(r0[q4]),     a1 = tf32r(r0[64 + q4]);
            unsigned a2 = tf32r(r0[q4 + 4]), a3 = tf32r(r0[64 + q4 + 4]);
            float c0 = dh0, c1 = dh1, c2 = dh0, c3 = dh1;

            #pragma unroll 4
            for (int q = 0; q < 32; q++) {
                float2 bp = b1f[(q << 2) | q4];
                float2 wv = w1f[(q << 5) | lane];
                float2 mv = mf[(q << 5) | lane];
                float h0, h1, h2, h3;
                mma_init(h0, h1, h2, h3, a0, a1, a2, a3,
                         __float_as_uint(wv.x), __float_as_uint(wv.y),
                         bp.x, bp.y, bp.x, bp.y);
                // tau-permutation alignment: A-frag = (c0, c2, c1, c3) relu'd
                unsigned x0 = tf32r(fmaxf(h0, 0.f));
                unsigned x1 = tf32r(fmaxf(h2, 0.f));
                unsigned x2 = tf32r(fmaxf(h1, 0.f));
                unsigned x3 = tf32r(fmaxf(h3, 0.f));
                mma_acc(c0, c1, c2, c3, x0, x1, x2, x3,
                        __float_as_uint(mv.x), __float_as_uint(mv.y));
            }

            size_t o1 = (size_t)(pe + g) * 8 + 2 * q4;
            float2 e1 = *(const float2*)(ea + o1);
            float2 e2v = *(const float2*)(ea + o1 + 64);
            *(float2*)(out + o1)      = make_float2(e1.x + c0, e1.y + c1);
            *(float2*)(out + o1 + 64) = make_float2(e2v.x + c2, e2v.y + c3);
        }
    }

    // ============ reset (last finisher) ============
    __syncthreads();
    if (t == 0) {
        __threadfence();
        if (atomicAdd(&g_finish, 1) == GRID - 1) {
            g_arrive = 0;
            g_release = 0;
            for (int i = 0; i < H_DIM; i++) { g_sum[i] = 0.f; g_sumsq[i] = 0.f; }
            __threadfence();
            g_finish = 0;
        }
    }
}

// -------- launch --------
extern "C" void kernel_launch(void* const* d_in, const int* in_sizes, int n_in,
                              void* d_out, int out_size) {
    (void)in_sizes; (void)n_in; (void)out_size;
    const float* edge_attr = (const float*)d_in[0];
    const float* nf        = (const float*)d_in[1];
    const int*   eidx      = (const int*)d_in[2];
    // d_in[3..8] = edge-encoder weights: dead code in the reference
    const float* W1    = (const float*)d_in[9];
    const float* b1    = (const float*)d_in[10];
    const float* gamma = (const float*)d_in[11];
    const float* beta  = (const float*)d_in[12];
    const float* W2    = (const float*)d_in[13];
    const float* b2    = (const float*)d_in[14];
    const float* Wv    = (const float*)d_in[15];
    const float* bv    = (const float*)d_in[16];
    const float* Wo    = (const float*)d_in[17];
    const float* bo    = (const float*)d_in[18];
    const float* Wp    = (const float*)d_in[19];
    const float* bp    = (const float*)d_in[20];
    float* out = (float*)d_out;

    fused<<<GRID, 256>>>(edge_attr, nf, eidx, W1, b1, gamma, beta,
                         W2, b2, Wv, bv, Wo, bo, Wp, bp, out);
}

// round 11
// speedup vs baseline: 2.4526x; 2.4526x over previous
#include <cuda_runtime.h>
#include <cstdint>

#define E_NUM   500000
#define H_DIM   256
#define PAIRS   (E_NUM / 2)      // 250000
#define BN_EPS  1e-5f
#define GRID    296              // 148 SMs x 2 co-resident blocks (3/SM is toxic: R4/R10)
#define PER1    848              // pairs/block for stats, blocks 1..295
#define NTILES  31250            // E/16 edge tiles for tensor phase 2
#define NWARPS  (GRID * 8)       // 2368 warps
#define NFAKE   103648           // zero-padded fake edges in stats (exact, see partition)

typedef unsigned long long u64;

// -------- device scratch (static, no allocation) --------
__device__ float g_sum[H_DIM];                     // zero-init
__device__ float g_sumsq[H_DIM];
__device__ __align__(16) float g_ncf[(size_t)E_NUM * 8];  // nc [E,8] (tf32-rounded), 16MB
__device__ float g_Craw[H_DIM * 8];                // W2@Wv@Wo@Wp
__device__ float g_biaspart[8];                    // b2@P2 + bv@P1 + bo@Wp + bp
__device__ unsigned g_arrive = 0;
__device__ volatile unsigned g_release = 0;
__device__ unsigned g_finish = 0;

// -------- misc helpers --------
__device__ __forceinline__ float wred(float v) {
    v += __shfl_down_sync(0xffffffffu, v, 16);
    v += __shfl_down_sync(0xffffffffu, v, 8);
    v += __shfl_down_sync(0xffffffffu, v, 4);
    v += __shfl_down_sync(0xffffffffu, v, 2);
    v += __shfl_down_sync(0xffffffffu, v, 1);
    return v;
}
__device__ __forceinline__ unsigned tf32r(float x) {
    unsigned u;
    asm("cvt.rna.tf32.f32 %0, %1;" : "=r"(u) : "f"(x));
    return u;
}
__device__ __forceinline__ void mma_init(float &d0, float &d1, float &d2, float &d3,
    unsigned a0, unsigned a1, unsigned a2, unsigned a3,
    unsigned b0, unsigned b1,
    float c0, float c1, float c2, float c3) {
    asm("mma.sync.aligned.m16n8k8.row.col.f32.tf32.tf32.f32 "
        "{%0,%1,%2,%3}, {%4,%5,%6,%7}, {%8,%9}, {%10,%11,%12,%13};"
        : "=f"(d0), "=f"(d1), "=f"(d2), "=f"(d3)
        : "r"(a0), "r"(a1), "r"(a2), "r"(a3), "r"(b0), "r"(b1),
          "f"(c0), "f"(c1), "f"(c2), "f"(c3));
}
__device__ __forceinline__ void mma_acc(float &c0, float &c1, float &c2, float &c3,
    unsigned a0, unsigned a1, unsigned a2, unsigned a3,
    unsigned b0, unsigned b1) {
    asm("mma.sync.aligned.m16n8k8.row.col.f32.tf32.tf32.f32 "
        "{%0,%1,%2,%3}, {%4,%5,%6,%7}, {%8,%9}, {%0,%1,%2,%3};"
        : "+f"(c0), "+f"(c1), "+f"(c2), "+f"(c3)
        : "r"(a0), "r"(a1), "r"(a2), "r"(a3), "r"(b0), "r"(b1));
}

__global__ void __launch_bounds__(256, 2)
fused(const float* __restrict__ ea, const float* __restrict__ nf,
      const int*   __restrict__ eidx,
      const float* __restrict__ W1, const float* __restrict__ b1,
      const float* __restrict__ gamma, const float* __restrict__ beta,
      const float* __restrict__ W2, const float* __restrict__ b2,
      const float* __restrict__ Wv, const float* __restrict__ bv,
      const float* __restrict__ Wo, const float* __restrict__ bo,
      const float* __restrict__ Wp, const float* __restrict__ bp,
      float* __restrict__ out)
{
    // s_buf: phase1 nc tile (512 rows x 8 f32 = 16KB) / block0 chain (2x2304 floats)
    __shared__ __align__(16) unsigned char s_buf[18432];
    __shared__ __align__(16) float2 w1frag[1024];   // GEMM1 B frags (both phases)
    __shared__ __align__(16) float2 mfrag[1024];    // GEMM2 B frags (tau-permuted)
    __shared__ float2 b1frag[128];                  // b1 col pairs
    __shared__ float dhf[8];
    __shared__ float a_s[H_DIM], c_s[H_DIM];

    const int t = threadIdx.x;
    const int b = blockIdx.x;
    const int lane = t & 31, warp = t >> 5;
    const int g = lane >> 2, q4 = lane & 3;

    // ---- build W1 / b1 fragment tables (used by phase 1 AND phase 2) ----
    for (int i = t; i < 1024; i += 256) {
        int q = i >> 5, l = i & 31;
        int kk = l & 3, nn = l >> 2;
        float w0 = W1[kk * H_DIM + q * 8 + nn];
        float w1v = W1[(kk + 4) * H_DIM + q * 8 + nn];
        w1frag[i] = make_float2(__uint_as_float(tf32r(w0)), __uint_as_float(tf32r(w1v)));
    }
    for (int i = t; i < 128; i += 256) {
        int q = i >> 2, qq = i & 3;
        b1frag[i] = make_float2(b1[q * 8 + 2 * qq], b1[q * 8 + 2 * qq + 1]);
    }
    __syncthreads();

    if (b == 0) {
        // ============ weight chain (overlaps the stats pass) ============
        float* bufA = (float*)s_buf;
        float* bufB = bufA + 2304;
        for (int i = t; i < H_DIM * 8; i += 256)
            bufA[(i >> 3) * 9 + (i & 7)] = Wp[i];
        __syncthreads();
        float biask = 0.f;
        for (int j = lane; j < H_DIM; j += 32) biask += bo[j] * bufA[j * 9 + warp];
        for (int jj = warp; jj < H_DIM; jj += 8) {
            float a0=0,a1=0,a2=0,a3=0,a4=0,a5=0,a6=0,a7=0;
            #pragma unroll
            for (int qb = 0; qb < 8; qb++) {
                int q = qb * 32 + lane;
                float av = Wo[jj * H_DIM + q];
                const float* ir = bufA + q * 9;
                a0 += av*ir[0]; a1 += av*ir[1]; a2 += av*ir[2]; a3 += av*ir[3];
                a4 += av*ir[4]; a5 += av*ir[5]; a6 += av*ir[6]; a7 += av*ir[7];
            }
            a0=wred(a0); a1=wred(a1); a2=wred(a2); a3=wred(a3);
            a4=wred(a4); a5=wred(a5); a6=wred(a6); a7=wred(a7);
            if (lane == 0) {
                float* orow = bufB + jj * 9;
                orow[0]=a0; orow[1]=a1; orow[2]=a2; orow[3]=a3;
                orow[4]=a4; orow[5]=a5; orow[6]=a6; orow[7]=a7;
            }
        }
        __syncthreads();
        for (int j = lane; j < H_DIM; j += 32) biask += bv[j] * bufB[j * 9 + warp];
        for (int jj = warp; jj < H_DIM; jj += 8) {
            float a0=0,a1=0,a2=0,a3=0,a4=0,a5=0,a6=0,a7=0;
            #pragma unroll
            for (int qb = 0; qb < 8; qb++) {
                int q = qb * 32 + lane;
                float av = Wv[jj * H_DIM + q];
                const float* ir = bufB + q * 9;
                a0 += av*ir[0]; a1 += av*ir[1]; a2 += av*ir[2]; a3 += av*ir[3];
                a4 += av*ir[4]; a5 += av*ir[5]; a6 += av*ir[6]; a7 += av*ir[7];
            }
            a0=wred(a0); a1=wred(a1); a2=wred(a2); a3=wred(a3);
            a4=wred(a4); a5=wred(a5); a6=wred(a6); a7=wred(a7);
            if (lane == 0) {
                float* orow = bufA + jj * 9;
                orow[0]=a0; orow[1]=a1; orow[2]=a2; orow[3]=a3;
                orow[4]=a4; orow[5]=a5; orow[6]=a6; orow[7]=a7;
            }
        }
        __syncthreads();
        for (int j = lane; j < H_DIM; j += 32) biask += b2[j] * bufA[j * 9 + warp];
        for (int jj = warp; jj < H_DIM; jj += 8) {
            float a0=0,a1=0,a2=0,a3=0,a4=0,a5=0,a6=0,a7=0;
            #pragma unroll
            for (int qb = 0; qb < 8; qb++) {
                int q = qb * 32 + lane;
                float av = W2[jj * H_DIM + q];
                const float* ir = bufA + q * 9;
                a0 += av*ir[0]; a1 += av*ir[1]; a2 += av*ir[2]; a3 += av*ir[3];
                a4 += av*ir[4]; a5 += av*ir[5]; a6 += av*ir[6]; a7 += av*ir[7];
            }
            a0=wred(a0); a1=wred(a1); a2=wred(a2); a3=wred(a3);
            a4=wred(a4); a5=wred(a5); a6=wred(a6); a7=wred(a7);
            if (lane == 0) {
                float* orow = g_Craw + jj * 8;
                orow[0]=a0; orow[1]=a1; orow[2]=a2; orow[3]=a3;
                orow[4]=a4; orow[5]=a5; orow[6]=a6; orow[7]=a7;
            }
        }
        biask = wred(biask);
        if (lane == 0) g_biaspart[warp] = biask + bp[warp];
    } else {
        // ============ phase 1: gather + tensor-core relu stats ============
        int s1 = (b - 1) * PER1;
        int e1 = s1 + PER1; if (e1 > PAIRS) e1 = PAIRS;
        float* tile = (float*)s_buf;          // [512 rows][8 cols]
        const float4* nf4 = (const float4*)nf;

        // per-warp chunk fragments: q = warp + 8*i
        float2 wv0 = w1frag[((warp +  0) << 5) | lane];
        float2 wv1 = w1frag[((warp +  8) << 5) | lane];
        float2 wv2 = w1frag[((warp + 16) << 5) | lane];
        float2 wv3 = w1frag[((warp + 24) << 5) | lane];
        float2 bp0 = b1frag[((warp +  0) << 2) | q4];
        float2 bp1 = b1frag[((warp +  8) << 2) | q4];
        float2 bp2 = b1frag[((warp + 16) << 2) | q4];
        float2 bp3 = b1frag[((warp + 24) << 2) | q4];

        float ss0[4] = {0,0,0,0}, ss1[4] = {0,0,0,0};
        float qq0[4] = {0,0,0,0}, qq1[4] = {0,0,0,0};

        for (int base = s1; base < e1; base += 256) {
            int cnt = e1 - base; if (cnt > 256) cnt = 256;
            __syncthreads();
            float4* row0 = (float4*)(tile + (2 * t) * 8);
            if (t < cnt) {
                int p  = base + t;
                int e0 = 2 * p;
                int sA = eidx[e0],         sB = eidx[e0 + 1];
                int dA = eidx[E_NUM + e0], dB = eidx[E_NUM + e0 + 1];
                float4 sa0 = nf4[2*sA], sa1 = nf4[2*sA+1];
                float4 da0 = nf4[2*dA], da1 = nf4[2*dA+1];
                float4 sb0 = nf4[2*sB], sb1 = nf4[2*sB+1];
                float4 db0 = nf4[2*dB], db1 = nf4[2*dB+1];
                // tf32-rounded nc values (stats & phase-2 consistent)
                float l0 = __uint_as_float(tf32r(0.5f*(sa0.x+da0.x)));
                float l1 = __uint_as_float(tf32r(0.5f*(sa0.y+da0.y)));
                float l2 = __uint_as_float(tf32r(0.5f*(sa0.z+da0.z)));
                float l3 = __uint_as_float(tf32r(0.5f*(sa0.w+da0.w)));
                float l4 = __uint_as_float(tf32r(0.5f*(sa1.x+da1.x)));
                float l5 = __uint_as_float(tf32r(0.5f*(sa1.y+da1.y)));
                float l6 = __uint_as_float(tf32r(0.5f*(sa1.z+da1.z)));
                float l7 = __uint_as_float(tf32r(0.5f*(sa1.w+da1.w)));
                float h0 = __uint_as_float(tf32r(0.5f*(sb0.x+db0.x)));
                float h1 = __uint_as_float(tf32r(0.5f*(sb0.y+db0.y)));
                float h2 = __uint_as_float(tf32r(0.5f*(sb0.z+db0.z)));
                float h3 = __uint_as_float(tf32r(0.5f*(sb0.w+db0.w)));
                float h4 = __uint_as_float(tf32r(0.5f*(sb1.x+db1.x)));
                float h5 = __uint_as_float(tf32r(0.5f*(sb1.y+db1.y)));
                float h6 = __uint_as_float(tf32r(0.5f*(sb1.z+db1.z)));
                float h7 = __uint_as_float(tf32r(0.5f*(sb1.w+db1.w)));
                float4 vl0 = make_float4(l0, l1, l2, l3), vl1 = make_float4(l4, l5, l6, l7);
                float4 vh0 = make_float4(h0, h1, h2, h3), vh1 = make_float4(h4, h5, h6, h7);
                row0[0] = vl0; row0[1] = vl1; row0[2] = vh0; row0[3] = vh1;
                float4* nr = (float4*)(g_ncf + (size_t)(2 * p) * 8);
                nr[0] = vl0; nr[1] = vl1; nr[2] = vh0; nr[3] = vh1;
            } else {
                float4 z = make_float4(0.f, 0.f, 0.f, 0.f);
                row0[0] = z; row0[1] = z; row0[2] = z; row0[3] = z;
            }
            __syncthreads();

            // stats: 32 edge-subtiles x my 4 chunks, one mma each
            #pragma unroll 4
            for (int et = 0; et < 32; et++) {
                int r0 = et * 16 + g;
                unsigned a0 = __float_as_uint(tile[r0 * 8 + q4]);
                unsigned a1 = __float_as_uint(tile[(r0 + 8) * 8 + q4]);
                unsigned a2 = __float_as_uint(tile[r0 * 8 + q4 + 4]);
                unsigned a3 = __float_as_uint(tile[(r0 + 8) * 8 + q4 + 4]);
                float h0, h1, h2, h3;
                mma_init(h0, h1, h2, h3, a0, a1, a2, a3,
                         __float_as_uint(wv0.x), __float_as_uint(wv0.y),
                         bp0.x, bp0.y, bp0.x, bp0.y);
                h0 = fmaxf(h0, 0.f); h1 = fmaxf(h1, 0.f);
                h2 = fmaxf(h2, 0.f); h3 = fmaxf(h3, 0.f);
                ss0[0] += h0 + h2; ss1[0] += h1 + h3;
                qq0[0] += h0*h0 + h2*h2; qq1[0] += h1*h1 + h3*h3;
                mma_init(h0, h1, h2, h3, a0, a1, a2, a3,
                         __float_as_uint(wv1.x), __float_as_uint(wv1.y),
                         bp1.x, bp1.y, bp1.x, bp1.y);
                h0 = fmaxf(h0, 0.f); h1 = fmaxf(h1, 0.f);
                h2 = fmaxf(h2, 0.f); h3 = fmaxf(h3, 0.f);
                ss0[1] += h0 + h2; ss1[1] += h1 + h3;
                qq0[1] += h0*h0 + h2*h2; qq1[1] += h1*h1 + h3*h3;
                mma_init(h0, h1, h2, h3, a0, a1, a2, a3,
                         __float_as_uint(wv2.x), __float_as_uint(wv2.y),
                         bp2.x, bp2.y, bp2.x, bp2.y);
                h0 = fmaxf(h0, 0.f); h1 = fmaxf(h1, 0.f);
                h2 = fmaxf(h2, 0.f); h3 = fmaxf(h3, 0.f);
                ss0[2] += h0 + h2; ss1[2] += h1 + h3;
                qq0[2] += h0*h0 + h2*h2; qq1[2] += h1*h1 + h3*h3;
                mma_init(h0, h1, h2, h3, a0, a1, a2, a3,
                         __float_as_uint(wv3.x), __float_as_uint(wv3.y),
                         bp3.x, bp3.y, bp3.x, bp3.y);
                h0 = fmaxf(h0, 0.f); h1 = fmaxf(h1, 0.f);
                h2 = fmaxf(h2, 0.f); h3 = fmaxf(h3, 0.f);
                ss0[3] += h0 + h2; ss1[3] += h1 + h3;
                qq0[3] += h0*h0 + h2*h2; qq1[3] += h1*h1 + h3*h3;
            }
        }

        // reduce over g lanes (xor 4, 8, 16) and atomically commit
        #pragma unroll
        for (int i = 0; i < 4; i++) {
            #pragma unroll
            for (int off = 4; off <= 16; off <<= 1) {
                ss0[i] += __shfl_xor_sync(0xffffffffu, ss0[i], off);
                ss1[i] += __shfl_xor_sync(0xffffffffu, ss1[i], off);
                qq0[i] += __shfl_xor_sync(0xffffffffu, qq0[i], off);
                qq1[i] += __shfl_xor_sync(0xffffffffu, qq1[i], off);
            }
            if (lane < 4) {
                int q = warp + 8 * i;
                int col = q * 8 + 2 * q4;
                atomicAdd(&g_sum[col],     ss0[i]);
                atomicAdd(&g_sum[col + 1], ss1[i]);
                atomicAdd(&g_sumsq[col],     qq0[i]);
                atomicAdd(&g_sumsq[col + 1], qq1[i]);
            }
        }
    }

    // ============ grid barrier ============
    __syncthreads();
    if (t == 0) {
        __threadfence();
        if (atomicAdd(&g_arrive, 1) == GRID - 1) {
            g_release = 1;
        } else {
            while (g_release == 0) { }
        }
        __threadfence();
    }
    __syncthreads();

    // ============ finalize BN (with fake-row correction), dh, mfrag ============
    {
        const float invE = 1.f / (float)E_NUM;
        float rb = fmaxf(b1[t], 0.f);
        float sum   = g_sum[t]   - (float)NFAKE * rb;
        float sumsq = g_sumsq[t] - (float)NFAKE * rb * rb;
        float mu  = sum * invE;
        float var = sumsq * invE - mu * mu;
        float aj  = gamma[t] * rsqrtf(var + BN_EPS);
        a_s[t] = aj;
        c_s[t] = beta[t] - mu * aj;
    }
    __syncthreads();
    {
        float acc = 0.f;
        for (int j = lane; j < H_DIM; j += 32) acc += c_s[j] * g_Craw[j * 8 + warp];
        acc = wred(acc);
        if (lane == 0) dhf[warp] = 0.5f * (acc + g_biaspart[warp]);
    }
    for (int i = t; i < 1024; i += 256) {
        int q = i >> 5, l = i & 31;
        int kk = l & 3, nn = l >> 2;
        // GEMM2 B rows tau-permuted: slot kk -> j = q*8+2kk; slot kk+4 -> j = q*8+2kk+1
        int j0 = q * 8 + 2 * kk;
        float m0 = 0.5f * a_s[j0] * g_Craw[j0 * 8 + nn];
        float m1 = 0.5f * a_s[j0 + 1] * g_Craw[(j0 + 1) * 8 + nn];
        mfrag[i] = make_float2(__uint_as_float(tf32r(m0)), __uint_as_float(tf32r(m1)));
    }
    __syncthreads();

    // ============ phase 2: tensor contraction, 2 tiles/warp interleaved ======
    {
        const int warp_gid = b * 8 + warp;
        const float dh0 = dhf[2 * q4], dh1 = dhf[2 * q4 + 1];

        int tau = warp_gid;
        for (; tau + NWARPS < NTILES; tau += 2 * NWARPS) {
            int peX = tau << 4;
            int peY = (tau + NWARPS) << 4;
            const float* rX0 = g_ncf + (size_t)(peX + g) * 8;
            const float* rY0 = g_ncf + (size_t)(peY + g) * 8;
            unsigned aX0 = tf32r(rX0[q4]),      aX1 = tf32r(rX0[64 + q4]);
            unsigned aX2 = tf32r(rX0[q4 + 4]),  aX3 = tf32r(rX0[64 + q4 + 4]);
            unsigned aY0 = tf32r(rY0[q4]),      aY1 = tf32r(rY0[64 + q4]);
            unsigned aY2 = tf32r(rY0[q4 + 4]),  aY3 = tf32r(rY0[64 + q4 + 4]);
            float cX0 = dh0, cX1 = dh1, cX2 = dh0, cX3 = dh1;
            float cY0 = dh0, cY1 = dh1, cY2 = dh0, cY3 = dh1;

            #pragma unroll 4
            for (int q = 0; q < 32; q++) {
                float2 bpv = b1frag[(q << 2) | q4];
                float2 wv = w1frag[(q << 5) | lane];
                float2 mv = mfrag[(q << 5) | lane];
                unsigned wb0 = __float_as_uint(wv.x), wb1 = __float_as_uint(wv.y);
                unsigned mb0 = __float_as_uint(mv.x), mb1 = __float_as_uint(mv.y);
                float hX0, hX1, hX2, hX3, hY0, hY1, hY2, hY3;
                mma_init(hX0, hX1, hX2, hX3, aX0, aX1, aX2, aX3, wb0, wb1,
                         bpv.x, bpv.y, bpv.x, bpv.y);
                mma_init(hY0, hY1, hY2, hY3, aY0, aY1, aY2, aY3, wb0, wb1,
                         bpv.x, bpv.y, bpv.x, bpv.y);
                unsigned xX0 = tf32r(fmaxf(hX0, 0.f));
                unsigned xX1 = tf32r(fmaxf(hX2, 0.f));
                unsigned xX2 = tf32r(fmaxf(hX1, 0.f));
                unsigned xX3 = tf32r(fmaxf(hX3, 0.f));
                unsigned xY0 = tf32r(fmaxf(hY0, 0.f));
                unsigned xY1 = tf32r(fmaxf(hY2, 0.f));
                unsigned xY2 = tf32r(fmaxf(hY1, 0.f));
                unsigned xY3 = tf32r(fmaxf(hY3, 0.f));
                mma_acc(cX0, cX1, cX2, cX3, xX0, xX1, xX2, xX3, mb0, mb1);
                mma_acc(cY0, cY1, cY2, cY3, xY0, xY1, xY2, xY3, mb0, mb1);
            }

            size_t oX = (size_t)(peX + g) * 8 + 2 * q4;
            size_t oY = (size_t)(peY + g) * 8 + 2 * q4;
            float2 eX1 = *(const float2*)(ea + oX);
            float2 eX2 = *(const float2*)(ea + oX + 64);
            float2 eY1 = *(const float2*)(ea + oY);
            float2 eY2 = *(const float2*)(ea + oY + 64);
            *(float2*)(out + oX)      = make_float2(eX1.x + cX0, eX1.y + cX1);
            *(float2*)(out + oX + 64) = make_float2(eX2.x + cX2, eX2.y + cX3);
            *(float2*)(out + oY)      = make_float2(eY1.x + cY0, eY1.y + cY1);
            *(float2*)(out + oY + 64) = make_float2(eY2.x + cY2, eY2.y + cY3);
        }
        if (tau < NTILES) {
            int pe = tau << 4;
            const float* r0 = g_ncf + (size_t)(pe + g) * 8;
            unsigned a0 = tf32r(r0[q4]),     a1 = tf32r(r0[64 + q4]);
            unsigned a2 = tf32r(r0[q4 + 4]), a3 = tf32r(r0[64 + q4 + 4]);
            float c0 = dh0, c1 = dh1, c2 = dh0, c3 = dh1;
            #pragma unroll 4
            for (int q = 0; q < 32; q++) {
                float2 bpv = b1frag[(q << 2) | q4];
                float2 wv = w1frag[(q << 5) | lane];
                float2 mv = mfrag[(q << 5) | lane];
                float h0, h1, h2, h3;
                mma_init(h0, h1, h2, h3, a0, a1, a2, a3,
                         __float_as_uint(wv.x), __float_as_uint(wv.y),
                         bpv.x, bpv.y, bpv.x, bpv.y);
                unsigned x0 = tf32r(fmaxf(h0, 0.f));
                unsigned x1 = tf32r(fmaxf(h2, 0.f));
                unsigned x2 = tf32r(fmaxf(h1, 0.f));
                unsigned x3 = tf32r(fmaxf(h3, 0.f));
                mma_acc(c0, c1, c2, c3, x0, x1, x2, x3,
                        __float_as_uint(mv.x), __float_as_uint(mv.y));
            }
            size_t o1 = (size_t)(pe + g) * 8 + 2 * q4;
            float2 e1 = *(const float2*)(ea + o1);
            float2 e2v = *(const float2*)(ea + o1 + 64);
            *(float2*)(out + o1)      = make_float2(e1.x + c0, e1.y + c1);
            *(float2*)(out + o1 + 64) = make_float2(e2v.x + c2, e2v.y + c3);
        }
    }

    // ============ reset (last finisher) ============
    __syncthreads();
    if (t == 0) {
        __threadfence();
        if (atomicAdd(&g_finish, 1) == GRID - 1) {
            g_arrive = 0;
            g_release = 0;
            for (int i = 0; i < H_DIM; i++) { g_sum[i] = 0.f; g_sumsq[i] = 0.f; }
            __threadfence();
            g_finish = 0;
        }
    }
}

// -------- launch --------
extern "C" void kernel_launch(void* const* d_in, const int* in_sizes, int n_in,
                              void* d_out, int out_size) {
    (void)in_sizes; (void)n_in; (void)out_size;
    const float* edge_attr = (const float*)d_in[0];
    const float* nf        = (const float*)d_in[1];
    const int*   eidx      = (const int*)d_in[2];
    // d_in[3..8] = edge-encoder weights: dead code in the reference
    const float* W1    = (const float*)d_in[9];
    const float* b1    = (const float*)d_in[10];
    const float* gamma = (const float*)d_in[11];
    const float* beta  = (const float*)d_in[12];
    const float* W2    = (const float*)d_in[13];
    const float* b2    = (const float*)d_in[14];
    const float* Wv    = (const float*)d_in[15];
    const float* bv    = (const float*)d_in[16];
    const float* Wo    = (const float*)d_in[17];
    const float* bo    = (const float*)d_in[18];
    const float* Wp    = (const float*)d_in[19];
    const float* bp    = (const float*)d_in[20];
    float* out = (float*)d_out;

    fused<<<GRID, 256>>>(edge_attr, nf, eidx, W1, b1, gamma, beta,
                         W2, b2, Wv, bv, Wo, bo, Wp, bp, out);
}

// round 12
// speedup vs baseline: 2.6551x; 1.0826x over previous
#include <cuda_runtime.h>
#include <cstdint>

#define E_NUM   500000
#define H_DIM   256
#define PAIRS   (E_NUM / 2)      // 250000
#define BN_EPS  1e-5f
#define GRID    296              // 148 SMs x 2 co-resident blocks (3/SM toxic: R4/R10)
#define PER1    848              // pairs/block for stats, blocks 1..295
#define NTILES  31250            // E/16 edge tiles for tensor phase 2
#define NWARPS  (GRID * 8)       // 2368 warps
#define NFAKE   103648           // zero-padded fake edges in stats (exact for PER1=848)

// -------- device scratch (static, no allocation) --------
__device__ float g_sum[H_DIM];                     // zero-init
__device__ float g_sumsq[H_DIM];
__device__ __align__(16) float g_ncf[(size_t)E_NUM * 8];  // nc [E,8] (tf32-rounded), 16MB
__device__ float g_Craw[H_DIM * 8];                // W2@Wv@Wo@Wp
__device__ float g_biaspart[8];                    // b2@P2 + bv@P1 + bo@Wp + bp
__device__ unsigned g_arrive = 0;
__device__ volatile unsigned g_release = 0;
__device__ unsigned g_finish = 0;

// -------- misc helpers --------
__device__ __forceinline__ float wred(float v) {
    v += __shfl_down_sync(0xffffffffu, v, 16);
    v += __shfl_down_sync(0xffffffffu, v, 8);
    v += __shfl_down_sync(0xffffffffu, v, 4);
    v += __shfl_down_sync(0xffffffffu, v, 2);
    v += __shfl_down_sync(0xffffffffu, v, 1);
    return v;
}
__device__ __forceinline__ unsigned tf32r(float x) {
    unsigned u;
    asm("cvt.rna.tf32.f32 %0, %1;" : "=r"(u) : "f"(x));
    return u;
}
__device__ __forceinline__ void mma_init(float &d0, float &d1, float &d2, float &d3,
    unsigned a0, unsigned a1, unsigned a2, unsigned a3,
    unsigned b0, unsigned b1,
    float c0, float c1, float c2, float c3) {
    asm("mma.sync.aligned.m16n8k8.row.col.f32.tf32.tf32.f32 "
        "{%0,%1,%2,%3}, {%4,%5,%6,%7}, {%8,%9}, {%10,%11,%12,%13};"
        : "=f"(d0), "=f"(d1), "=f"(d2), "=f"(d3)
        : "r"(a0), "r"(a1), "r"(a2), "r"(a3), "r"(b0), "r"(b1),
          "f"(c0), "f"(c1), "f"(c2), "f"(c3));
}
__device__ __forceinline__ void mma_acc(float &c0, float &c1, float &c2, float &c3,
    unsigned a0, unsigned a1, unsigned a2, unsigned a3,
    unsigned b0, unsigned b1) {
    asm("mma.sync.aligned.m16n8k8.row.col.f32.tf32.tf32.f32 "
        "{%0,%1,%2,%3}, {%4,%5,%6,%7}, {%8,%9}, {%0,%1,%2,%3};"
        : "+f"(c0), "+f"(c1), "+f"(c2), "+f"(c3)
        : "r"(a0), "r"(a1), "r"(a2), "r"(a3), "r"(b0), "r"(b1));
}

// gather one 256-pair tile into smem buffer (zero-pad invalid rows) + g_ncf
__device__ __forceinline__ void gather_tile(
    int base, int e1, float* buf, int t,
    const int* __restrict__ eidx, const float4* __restrict__ nf4)
{
    float4* row0 = (float4*)(buf + (2 * t) * 8);
    int p = base + t;
    if (p < e1) {
        int e0 = 2 * p;
        int sA = eidx[e0],         sB = eidx[e0 + 1];
        int dA = eidx[E_NUM + e0], dB = eidx[E_NUM + e0 + 1];
        float4 sa0 = nf4[2*sA], sa1 = nf4[2*sA+1];
        float4 da0 = nf4[2*dA], da1 = nf4[2*dA+1];
        float4 sb0 = nf4[2*sB], sb1 = nf4[2*sB+1];
        float4 db0 = nf4[2*dB], db1 = nf4[2*dB+1];
        float4 vl0 = make_float4(__uint_as_float(tf32r(0.5f*(sa0.x+da0.x))),
                                 __uint_as_float(tf32r(0.5f*(sa0.y+da0.y))),
                                 __uint_as_float(tf32r(0.5f*(sa0.z+da0.z))),
                                 __uint_as_float(tf32r(0.5f*(sa0.w+da0.w))));
        float4 vl1 = make_float4(__uint_as_float(tf32r(0.5f*(sa1.x+da1.x))),
                                 __uint_as_float(tf32r(0.5f*(sa1.y+da1.y))),
                                 __uint_as_float(tf32r(0.5f*(sa1.z+da1.z))),
                                 __uint_as_float(tf32r(0.5f*(sa1.w+da1.w))));
        float4 vh0 = make_float4(__uint_as_float(tf32r(0.5f*(sb0.x+db0.x))),
                                 __uint_as_float(tf32r(0.5f*(sb0.y+db0.y))),
                                 __uint_as_float(tf32r(0.5f*(sb0.z+db0.z))),
                                 __uint_as_float(tf32r(0.5f*(sb0.w+db0.w))));
        float4 vh1 = make_float4(__uint_as_float(tf32r(0.5f*(sb1.x+db1.x))),
                                 __uint_as_float(tf32r(0.5f*(sb1.y+db1.y))),
                                 __uint_as_float(tf32r(0.5f*(sb1.z+db1.z))),
                                 __uint_as_float(tf32r(0.5f*(sb1.w+db1.w))));
        row0[0] = vl0; row0[1] = vl1; row0[2] = vh0; row0[3] = vh1;
        float4* nr = (float4*)(g_ncf + (size_t)(2 * p) * 8);
        nr[0] = vl0; nr[1] = vl1; nr[2] = vh0; nr[3] = vh1;
    } else {
        float4 z = make_float4(0.f, 0.f, 0.f, 0.f);
        row0[0] = z; row0[1] = z; row0[2] = z; row0[3] = z;
    }
}

__global__ void __launch_bounds__(256, 2)
fused(const float* __restrict__ ea, const float* __restrict__ nf,
      const int*   __restrict__ eidx,
      const float* __restrict__ W1, const float* __restrict__ b1,
      const float* __restrict__ gamma, const float* __restrict__ beta,
      const float* __restrict__ W2, const float* __restrict__ b2,
      const float* __restrict__ Wv, const float* __restrict__ bv,
      const float* __restrict__ Wo, const float* __restrict__ bo,
      const float* __restrict__ Wp, const float* __restrict__ bp,
      float* __restrict__ out)
{
    // s_buf: phase1 buf0 (16KB of it) / block0 chain (2x2304 floats = 18KB)
    __shared__ __align__(16) unsigned char s_buf[18432];
    __shared__ __align__(16) float tile2[4096];     // phase1 buf1 (16KB)
    __shared__ __align__(16) float2 w1frag[1024];   // GEMM1 B frags (both phases)
    __shared__ __align__(16) float2 mfrag[1024];    // GEMM2 B frags (tau-permuted)
    __shared__ float2 b1frag[128];                  // b1 col pairs
    __shared__ float dhf[8];
    __shared__ float a_s[H_DIM], c_s[H_DIM];

    const int t = threadIdx.x;
    const int b = blockIdx.x;
    const int lane = t & 31, warp = t >> 5;
    const int g = lane >> 2, q4 = lane & 3;

    // ---- W1 / b1 fragment tables (phase 1 AND phase 2) ----
    for (int i = t; i < 1024; i += 256) {
        int q = i >> 5, l = i & 31;
        int kk = l & 3, nn = l >> 2;
        float w0 = W1[kk * H_DIM + q * 8 + nn];
        float w1v = W1[(kk + 4) * H_DIM + q * 8 + nn];
        w1frag[i] = make_float2(__uint_as_float(tf32r(w0)), __uint_as_float(tf32r(w1v)));
    }
    for (int i = t; i < 128; i += 256) {
        int q = i >> 2, qq = i & 3;
        b1frag[i] = make_float2(b1[q * 8 + 2 * qq], b1[q * 8 + 2 * qq + 1]);
    }
    __syncthreads();

    if (b == 0) {
        // ============ weight chain (overlaps the stats pass) ============
        float* bufA = (float*)s_buf;
        float* bufB = bufA + 2304;
        for (int i = t; i < H_DIM * 8; i += 256)
            bufA[(i >> 3) * 9 + (i & 7)] = Wp[i];
        __syncthreads();
        float biask = 0.f;
        for (int j = lane; j < H_DIM; j += 32) biask += bo[j] * bufA[j * 9 + warp];
        for (int jj = warp; jj < H_DIM; jj += 8) {
            float a0=0,a1=0,a2=0,a3=0,a4=0,a5=0,a6=0,a7=0;
            #pragma unroll
            for (int qb = 0; qb < 8; qb++) {
                int q = qb * 32 + lane;
                float av = Wo[jj * H_DIM + q];
                const float* ir = bufA + q * 9;
                a0 += av*ir[0]; a1 += av*ir[1]; a2 += av*ir[2]; a3 += av*ir[3];
                a4 += av*ir[4]; a5 += av*ir[5]; a6 += av*ir[6]; a7 += av*ir[7];
            }
            a0=wred(a0); a1=wred(a1); a2=wred(a2); a3=wred(a3);
            a4=wred(a4); a5=wred(a5); a6=wred(a6); a7=wred(a7);
            if (lane == 0) {
                float* orow = bufB + jj * 9;
                orow[0]=a0; orow[1]=a1; orow[2]=a2; orow[3]=a3;
                orow[4]=a4; orow[5]=a5; orow[6]=a6; orow[7]=a7;
            }
        }
        __syncthreads();
        for (int j = lane; j < H_DIM; j += 32) biask += bv[j] * bufB[j * 9 + warp];
        for (int jj = warp; jj < H_DIM; jj += 8) {
            float a0=0,a1=0,a2=0,a3=0,a4=0,a5=0,a6=0,a7=0;
            #pragma unroll
            for (int qb = 0; qb < 8; qb++) {
                int q = qb * 32 + lane;
                float av = Wv[jj * H_DIM + q];
                const float* ir = bufB + q * 9;
                a0 += av*ir[0]; a1 += av*ir[1]; a2 += av*ir[2]; a3 += av*ir[3];
                a4 += av*ir[4]; a5 += av*ir[5]; a6 += av*ir[6]; a7 += av*ir[7];
            }
            a0=wred(a0); a1=wred(a1); a2=wred(a2); a3=wred(a3);
            a4=wred(a4); a5=wred(a5); a6=wred(a6); a7=wred(a7);
            if (lane == 0) {
                float* orow = bufA + jj * 9;
                orow[0]=a0; orow[1]=a1; orow[2]=a2; orow[3]=a3;
                orow[4]=a4; orow[5]=a5; orow[6]=a6; orow[7]=a7;
            }
        }
        __syncthreads();
        for (int j = lane; j < H_DIM; j += 32) biask += b2[j] * bufA[j * 9 + warp];
        for (int jj = warp; jj < H_DIM; jj += 8) {
            float a0=0,a1=0,a2=0,a3=0,a4=0,a5=0,a6=0,a7=0;
            #pragma unroll
            for (int qb = 0; qb < 8; qb++) {
                int q = qb * 32 + lane;
                float av = W2[jj * H_DIM + q];
                const float* ir = bufA + q * 9;
                a0 += av*ir[0]; a1 += av*ir[1]; a2 += av*ir[2]; a3 += av*ir[3];
                a4 += av*ir[4]; a5 += av*ir[5]; a6 += av*ir[6]; a7 += av*ir[7];
            }
            a0=wred(a0); a1=wred(a1); a2=wred(a2); a3=wred(a3);
            a4=wred(a4); a5=wred(a5); a6=wred(a6); a7=wred(a7);
            if (lane == 0) {
                float* orow = g_Craw + jj * 8;
                orow[0]=a0; orow[1]=a1; orow[2]=a2; orow[3]=a3;
                orow[4]=a4; orow[5]=a5; orow[6]=a6; orow[7]=a7;
            }
        }
        biask = wred(biask);
        if (lane == 0) g_biaspart[warp] = biask + bp[warp];
    } else {
        // ===== phase 1: double-buffered gather + tensor-core relu stats =====
        int s1 = (b - 1) * PER1;
        int e1 = s1 + PER1; if (e1 > PAIRS) e1 = PAIRS;
        const float4* nf4 = (const float4*)nf;
        float* bufs[2] = { (float*)s_buf, tile2 };
        const int nt = (e1 - s1 + 255) >> 8;

        float2 wv0 = w1frag[((warp +  0) << 5) | lane];
        float2 wv1 = w1frag[((warp +  8) << 5) | lane];
        float2 wv2 = w1frag[((warp + 16) << 5) | lane];
        float2 wv3 = w1frag[((warp + 24) << 5) | lane];
        float2 bp0 = b1frag[((warp +  0) << 2) | q4];
        float2 bp1 = b1frag[((warp +  8) << 2) | q4];
        float2 bp2 = b1frag[((warp + 16) << 2) | q4];
        float2 bp3 = b1frag[((warp + 24) << 2) | q4];

        float ss0[4] = {0,0,0,0}, ss1[4] = {0,0,0,0};
        float qq0[4] = {0,0,0,0}, qq1[4] = {0,0,0,0};

        gather_tile(s1, e1, bufs[0], t, eidx, nf4);
        __syncthreads();

        for (int it = 0; it < nt; it++) {
            // prefetch next tile into the other buffer (overlaps compute below)
            if (it + 1 < nt)
                gather_tile(s1 + (it + 1) * 256, e1, bufs[(it + 1) & 1], t, eidx, nf4);

            const float* tile = bufs[it & 1];
            #pragma unroll 4
            for (int et = 0; et < 32; et++) {
                int r0 = et * 16 + g;
                unsigned a0 = __float_as_uint(tile[r0 * 8 + q4]);
                unsigned a1 = __float_as_uint(tile[(r0 + 8) * 8 + q4]);
                unsigned a2 = __float_as_uint(tile[r0 * 8 + q4 + 4]);
                unsigned a3 = __float_as_uint(tile[(r0 + 8) * 8 + q4 + 4]);
                float h0, h1, h2, h3;
                mma_init(h0, h1, h2, h3, a0, a1, a2, a3,
                         __float_as_uint(wv0.x), __float_as_uint(wv0.y),
                         bp0.x, bp0.y, bp0.x, bp0.y);
                h0 = fmaxf(h0, 0.f); h1 = fmaxf(h1, 0.f);
                h2 = fmaxf(h2, 0.f); h3 = fmaxf(h3, 0.f);
                ss0[0] += h0; ss0[0] += h2; ss1[0] += h1; ss1[0] += h3;
                qq0[0] = fmaf(h0, h0, qq0[0]); qq0[0] = fmaf(h2, h2, qq0[0]);
                qq1[0] = fmaf(h1, h1, qq1[0]); qq1[0] = fmaf(h3, h3, qq1[0]);
                mma_init(h0, h1, h2, h3, a0, a1, a2, a3,
                         __float_as_uint(wv1.x), __float_as_uint(wv1.y),
                         bp1.x, bp1.y, bp1.x, bp1.y);
                h0 = fmaxf(h0, 0.f); h1 = fmaxf(h1, 0.f);
                h2 = fmaxf(h2, 0.f); h3 = fmaxf(h3, 0.f);
                ss0[1] += h0; ss0[1] += h2; ss1[1] += h1; ss1[1] += h3;
                qq0[1] = fmaf(h0, h0, qq0[1]); qq0[1] = fmaf(h2, h2, qq0[1]);
                qq1[1] = fmaf(h1, h1, qq1[1]); qq1[1] = fmaf(h3, h3, qq1[1]);
                mma_init(h0, h1, h2, h3, a0, a1, a2, a3,
                         __float_as_uint(wv2.x), __float_as_uint(wv2.y),
                         bp2.x, bp2.y, bp2.x, bp2.y);
                h0 = fmaxf(h0, 0.f); h1 = fmaxf(h1, 0.f);
                h2 = fmaxf(h2, 0.f); h3 = fmaxf(h3, 0.f);
                ss0[2] += h0; ss0[2] += h2; ss1[2] += h1; ss1[2] += h3;
                qq0[2] = fmaf(h0, h0, qq0[2]); qq0[2] = fmaf(h2, h2, qq0[2]);
                qq1[2] = fmaf(h1, h1, qq1[2]); qq1[2] = fmaf(h3, h3, qq1[2]);
                mma_init(h0, h1, h2, h3, a0, a1, a2, a3,
                         __float_as_uint(wv3.x), __float_as_uint(wv3.y),
                         bp3.x, bp3.y, bp3.x, bp3.y);
                h0 = fmaxf(h0, 0.f); h1 = fmaxf(h1, 0.f);
                h2 = fmaxf(h2, 0.f); h3 = fmaxf(h3, 0.f);
                ss0[3] += h0; ss0[3] += h2; ss1[3] += h1; ss1[3] += h3;
                qq0[3] = fmaf(h0, h0, qq0[3]); qq0[3] = fmaf(h2, h2, qq0[3]);
                qq1[3] = fmaf(h1, h1, qq1[3]); qq1[3] = fmaf(h3, h3, qq1[3]);
            }
            __syncthreads();   // next buffer fully written; current fully read
        }

        // reduce over g lanes (xor 4, 8, 16) and atomically commit
        #pragma unroll
        for (int i = 0; i < 4; i++) {
            #pragma unroll
            for (int off = 4; off <= 16; off <<= 1) {
                ss0[i] += __shfl_xor_sync(0xffffffffu, ss0[i], off);
                ss1[i] += __shfl_xor_sync(0xffffffffu, ss1[i], off);
                qq0[i] += __shfl_xor_sync(0xffffffffu, qq0[i], off);
                qq1[i] += __shfl_xor_sync(0xffffffffu, qq1[i], off);
            }
            if (lane < 4) {
                int q = warp + 8 * i;
                int col = q * 8 + 2 * q4;
                atomicAdd(&g_sum[col],     ss0[i]);
                atomicAdd(&g_sum[col + 1], ss1[i]);
                atomicAdd(&g_sumsq[col],     qq0[i]);
                atomicAdd(&g_sumsq[col + 1], qq1[i]);
            }
        }
    }

    // ============ grid barrier ============
    __syncthreads();
    if (t == 0) {
        __threadfence();
        if (atomicAdd(&g_arrive, 1) == GRID - 1) {
            g_release = 1;
        } else {
            while (g_release == 0) { }
        }
        __threadfence();
    }
    __syncthreads();

    // ============ finalize BN (fake-row corrected), dh, mfrag ============
    {
        const float invE = 1.f / (float)E_NUM;
        float rb = fmaxf(b1[t], 0.f);
        float sum   = g_sum[t]   - (float)NFAKE * rb;
        float sumsq = g_sumsq[t] - (float)NFAKE * rb * rb;
        float mu  = sum * invE;
        float var = sumsq * invE - mu * mu;
        float aj  = gamma[t] * rsqrtf(var + BN_EPS);
        a_s[t] = aj;
        c_s[t] = beta[t] - mu * aj;
    }
    __syncthreads();
    {
        float acc = 0.f;
        for (int j = lane; j < H_DIM; j += 32) acc += c_s[j] * g_Craw[j * 8 + warp];
        acc = wred(acc);
        if (lane == 0) dhf[warp] = 0.5f * (acc + g_biaspart[warp]);
    }
    for (int i = t; i < 1024; i += 256) {
        int q = i >> 5, l = i & 31;
        int kk = l & 3, nn = l >> 2;
        // GEMM2 B rows tau-permuted: slot kk -> j = q*8+2kk; slot kk+4 -> j = q*8+2kk+1
        int j0 = q * 8 + 2 * kk;
        float m0 = 0.5f * a_s[j0] * g_Craw[j0 * 8 + nn];
        float m1 = 0.5f * a_s[j0 + 1] * g_Craw[(j0 + 1) * 8 + nn];
        mfrag[i] = make_float2(__uint_as_float(tf32r(m0)), __uint_as_float(tf32r(m1)));
    }
    __syncthreads();

    // ============ phase 2: tensor contraction, 2 tiles/warp interleaved ======
    {
        const int warp_gid = b * 8 + warp;
        const float dh0 = dhf[2 * q4], dh1 = dhf[2 * q4 + 1];

        int tau = warp_gid;
        for (; tau + NWARPS < NTILES; tau += 2 * NWARPS) {
            int peX = tau << 4;
            int peY = (tau + NWARPS) << 4;
            const float* rX0 = g_ncf + (size_t)(peX + g) * 8;
            const float* rY0 = g_ncf + (size_t)(peY + g) * 8;
            // values already tf32-rounded in phase 1 — reinterpret, no cvt
            unsigned aX0 = __float_as_uint(rX0[q4]);
            unsigned aX1 = __float_as_uint(rX0[64 + q4]);
            unsigned aX2 = __float_as_uint(rX0[q4 + 4]);
            unsigned aX3 = __float_as_uint(rX0[64 + q4 + 4]);
            unsigned aY0 = __float_as_uint(rY0[q4]);
            unsigned aY1 = __float_as_uint(rY0[64 + q4]);
            unsigned aY2 = __float_as_uint(rY0[q4 + 4]);
            unsigned aY3 = __float_as_uint(rY0[64 + q4 + 4]);
            float cX0 = dh0, cX1 = dh1, cX2 = dh0, cX3 = dh1;
            float cY0 = dh0, cY1 = dh1, cY2 = dh0, cY3 = dh1;

            #pragma unroll 4
            for (int q = 0; q < 32; q++) {
                float2 bpv = b1frag[(q << 2) | q4];
                float2 wv = w1frag[(q << 5) | lane];
                float2 mv = mfrag[(q << 5) | lane];
                unsigned wb0 = __float_as_uint(wv.x), wb1 = __float_as_uint(wv.y);
                unsigned mb0 = __float_as_uint(mv.x), mb1 = __float_as_uint(mv.y);
                float hX0, hX1, hX2, hX3, hY0, hY1, hY2, hY3;
                mma_init(hX0, hX1, hX2, hX3, aX0, aX1, aX2, aX3, wb0, wb1,
                         bpv.x, bpv.y, bpv.x, bpv.y);
                mma_init(hY0, hY1, hY2, hY3, aY0, aY1, aY2, aY3, wb0, wb1,
                         bpv.x, bpv.y, bpv.x, bpv.y);
                // raw fp32 h into HMMA.TF32 (HW truncates mantissa); tau-permuted order
                unsigned xX0 = __float_as_uint(fmaxf(hX0, 0.f));
                unsigned xX1 = __float_as_uint(fmaxf(hX2, 0.f));
                unsigned xX2 = __float_as_uint(fmaxf(hX1, 0.f));
                unsigned xX3 = __float_as_uint(fmaxf(hX3, 0.f));
                unsigned xY0 = __float_as_uint(fmaxf(hY0, 0.f));
                unsigned xY1 = __float_as_uint(fmaxf(hY2, 0.f));
                unsigned xY2 = __float_as_uint(fmaxf(hY1, 0.f));
                unsigned xY3 = __float_as_uint(fmaxf(hY3, 0.f));
                mma_acc(cX0, cX1, cX2, cX3, xX0, xX1, xX2, xX3, mb0, mb1);
                mma_acc(cY0, cY1, cY2, cY3, xY0, xY1, xY2, xY3, mb0, mb1);
            }

            size_t oX = (size_t)(peX + g) * 8 + 2 * q4;
            size_t oY = (size_t)(peY + g) * 8 + 2 * q4;
            float2 eX1 = *(const float2*)(ea + oX);
            float2 eX2 = *(const float2*)(ea + oX + 64);
            float2 eY1 = *(const float2*)(ea + oY);
            float2 eY2 = *(const float2*)(ea + oY + 64);
            *(float2*)(out + oX)      = make_float2(eX1.x + cX0, eX1.y + cX1);
            *(float2*)(out + oX + 64) = make_float2(eX2.x + cX2, eX2.y + cX3);
            *(float2*)(out + oY)      = make_float2(eY1.x + cY0, eY1.y + cY1);
            *(float2*)(out + oY + 64) = make_float2(eY2.x + cY2, eY2.y + cY3);
        }
        if (tau < NTILES) {
            int pe = tau << 4;
            const float* r0 = g_ncf + (size_t)(pe + g) * 8;
            unsigned a0 = __float_as_uint(r0[q4]);
            unsigned a1 = __float_as_uint(r0[64 + q4]);
            unsigned a2 = __float_as_uint(r0[q4 + 4]);
            unsigned a3 = __float_as_uint(r0[64 + q4 + 4]);
            float c0 = dh0, c1 = dh1, c2 = dh0, c3 = dh1;
            #pragma unroll 4
            for (int q = 0; q < 32; q++) {
                float2 bpv = b1frag[(q << 2) | q4];
                float2 wv = w1frag[(q << 5) | lane];
                float2 mv = mfrag[(q << 5) | lane];
                float h0, h1, h2, h3;
                mma_init(h0, h1, h2, h3, a0, a1, a2, a3,
                         __float_as_uint(wv.x), __float_as_uint(wv.y),
                         bpv.x, bpv.y, bpv.x, bpv.y);
                unsigned x0 = __float_as_uint(fmaxf(h0, 0.f));
                unsigned x1 = __float_as_uint(fmaxf(h2, 0.f));
                unsigned x2 = __float_as_uint(fmaxf(h1, 0.f));
                unsigned x3 = __float_as_uint(fmaxf(h3, 0.f));
                mma_acc(c0, c1, c2, c3, x0, x1, x2, x3,
                        __float_as_uint(mv.x), __float_as_uint(mv.y));
            }
            size_t o1 = (size_t)(pe + g) * 8 + 2 * q4;
            float2 e1 = *(const float2*)(ea + o1);
            float2 e2v = *(const float2*)(ea + o1 + 64);
            *(float2*)(out + o1)      = make_float2(e1.x + c0, e1.y + c1);
            *(float2*)(out + o1 + 64) = make_float2(e2v.x + c2, e2v.y + c3);
        }
    }

    // ============ reset (last finisher) ============
    __syncthreads();
    if (t == 0) {
        __threadfence();
        if (atomicAdd(&g_finish, 1) == GRID - 1) {
            g_arrive = 0;
            g_release = 0;
            for (int i = 0; i < H_DIM; i++) { g_sum[i] = 0.f; g_sumsq[i] = 0.f; }
            __threadfence();
            g_finish = 0;
        }
    }
}

// -------- launch --------
extern "C" void kernel_launch(void* const* d_in, const int* in_sizes, int n_in,
                              void* d_out, int out_size) {
    (void)in_sizes; (void)n_in; (void)out_size;
    const float* edge_attr = (const float*)d_in[0];
    const float* nf        = (const float*)d_in[1];
    const int*   eidx      = (const int*)d_in[2];
    // d_in[3..8] = edge-encoder weights: dead code in the reference
    const float* W1    = (const float*)d_in[9];
    const float* b1    = (const float*)d_in[10];
    const float* gamma = (const float*)d_in[11];
    const float* beta  = (const float*)d_in[12];
    const float* W2    = (const float*)d_in[13];
    const float* b2    = (const float*)d_in[14];
    const float* Wv    = (const float*)d_in[15];
    const float* bv    = (const float*)d_in[16];
    const float* Wo    = (const float*)d_in[17];
    const float* bo    = (const float*)d_in[18];
    const float* Wp    = (const float*)d_in[19];
    const float* bp    = (const float*)d_in[20];
    float* out = (float*)d_out;

    fused<<<GRID, 256>>>(edge_attr, nf, eidx, W1, b1, gamma, beta,
                         W2, b2, Wv, bv, Wo, bo, Wp, bp, out);
}

// round 13
// speedup vs baseline: 2.7122x; 1.0215x over previous
#include <cuda_runtime.h>
#include <cstdint>

#define E_NUM   500000
#define H_DIM   256
#define PAIRS   (E_NUM / 2)      // 250000
#define BN_EPS  1e-5f
#define GRID    296              // 148 SMs x 2 co-resident blocks (3/SM toxic: R4/R10)
#define PER1    848              // pairs/block for stats, blocks 1..295
#define NTILES  31250            // E/16 edge tiles for tensor phase 2
#define NWARPS  (GRID * 8)       // 2368 warps
#define NFAKE   103648           // zero-padded fake edges in stats (exact for PER1=848)

typedef unsigned long long u64;

// -------- device scratch (static, no allocation) --------
__device__ float g_sum[H_DIM];                     // zero-init
__device__ float g_sumsq[H_DIM];
__device__ __align__(16) float g_ncf[(size_t)E_NUM * 8];  // raw (src+tgt) [E,8], 16MB
__device__ float g_Craw[H_DIM * 8];                // W2@Wv@Wo@Wp
__device__ float g_biaspart[8];                    // b2@P2 + bv@P1 + bo@Wp + bp
__device__ unsigned g_arrive = 0;
__device__ volatile unsigned g_release = 0;
__device__ unsigned g_finish = 0;

// -------- helpers --------
__device__ __forceinline__ float wred(float v) {
    v += __shfl_down_sync(0xffffffffu, v, 16);
    v += __shfl_down_sync(0xffffffffu, v, 8);
    v += __shfl_down_sync(0xffffffffu, v, 4);
    v += __shfl_down_sync(0xffffffffu, v, 2);
    v += __shfl_down_sync(0xffffffffu, v, 1);
    return v;
}
__device__ __forceinline__ unsigned tf32r(float x) {
    unsigned u;
    asm("cvt.rna.tf32.f32 %0, %1;" : "=r"(u) : "f"(x));
    return u;
}
__device__ __forceinline__ u64 pack2(float lo, float hi) {
    u64 r;
    asm("mov.b64 %0, {%1, %2};" : "=l"(r)
        : "r"(__float_as_uint(lo)), "r"(__float_as_uint(hi)));
    return r;
}
__device__ __forceinline__ void unpack2(u64 v, float &lo, float &hi) {
    unsigned int a, b;
    asm("mov.b64 {%0, %1}, %2;" : "=r"(a), "=r"(b) : "l"(v));
    lo = __uint_as_float(a); hi = __uint_as_float(b);
}
__device__ __forceinline__ u64 fma2(u64 a, u64 b, u64 c) {
    u64 d;
    asm("fma.rn.f32x2 %0, %1, %2, %3;" : "=l"(d) : "l"(a), "l"(b), "l"(c));
    return d;
}
__device__ __forceinline__ u64 add2(u64 a, u64 b) {
    u64 d;
    asm("add.rn.f32x2 %0, %1, %2;" : "=l"(d) : "l"(a), "l"(b));
    return d;
}
__device__ __forceinline__ void mma_init(float &d0, float &d1, float &d2, float &d3,
    unsigned a0, unsigned a1, unsigned a2, unsigned a3,
    unsigned b0, unsigned b1,
    float c0, float c1, float c2, float c3) {
    asm("mma.sync.aligned.m16n8k8.row.col.f32.tf32.tf32.f32 "
        "{%0,%1,%2,%3}, {%4,%5,%6,%7}, {%8,%9}, {%10,%11,%12,%13};"
        : "=f"(d0), "=f"(d1), "=f"(d2), "=f"(d3)
        : "r"(a0), "r"(a1), "r"(a2), "r"(a3), "r"(b0), "r"(b1),
          "f"(c0), "f"(c1), "f"(c2), "f"(c3));
}
__device__ __forceinline__ void mma_acc(float &c0, float &c1, float &c2, float &c3,
    unsigned a0, unsigned a1, unsigned a2, unsigned a3,
    unsigned b0, unsigned b1) {
    asm("mma.sync.aligned.m16n8k8.row.col.f32.tf32.tf32.f32 "
        "{%0,%1,%2,%3}, {%4,%5,%6,%7}, {%8,%9}, {%0,%1,%2,%3};"
        : "+f"(c0), "+f"(c1), "+f"(c2), "+f"(c3)
        : "r"(a0), "r"(a1), "r"(a2), "r"(a3), "r"(b0), "r"(b1));
}

// gather one 256-pair tile: raw (src+tgt), no cvt, no 0.5 (folded into W1)
__device__ __forceinline__ void gather_tile(
    int base, int e1, float* buf, int t,
    const int* __restrict__ eidx, const float4* __restrict__ nf4)
{
    float4* row0 = (float4*)(buf + (2 * t) * 8);
    int p = base + t;
    if (p < e1) {
        int e0 = 2 * p;
        int sA = eidx[e0],         sB = eidx[e0 + 1];
        int dA = eidx[E_NUM + e0], dB = eidx[E_NUM + e0 + 1];
        float4 sa0 = nf4[2*sA], sa1 = nf4[2*sA+1];
        float4 da0 = nf4[2*dA], da1 = nf4[2*dA+1];
        float4 sb0 = nf4[2*sB], sb1 = nf4[2*sB+1];
        float4 db0 = nf4[2*dB], db1 = nf4[2*dB+1];
        float4 vl0 = make_float4(sa0.x+da0.x, sa0.y+da0.y, sa0.z+da0.z, sa0.w+da0.w);
        float4 vl1 = make_float4(sa1.x+da1.x, sa1.y+da1.y, sa1.z+da1.z, sa1.w+da1.w);
        float4 vh0 = make_float4(sb0.x+db0.x, sb0.y+db0.y, sb0.z+db0.z, sb0.w+db0.w);
        float4 vh1 = make_float4(sb1.x+db1.x, sb1.y+db1.y, sb1.z+db1.z, sb1.w+db1.w);
        row0[0] = vl0; row0[1] = vl1; row0[2] = vh0; row0[3] = vh1;
        float4* nr = (float4*)(g_ncf + (size_t)(2 * p) * 8);
        nr[0] = vl0; nr[1] = vl1; nr[2] = vh0; nr[3] = vh1;
    } else {
        float4 z = make_float4(0.f, 0.f, 0.f, 0.f);
        row0[0] = z; row0[1] = z; row0[2] = z; row0[3] = z;
    }
}

__global__ void __launch_bounds__(256, 2)
fused(const float* __restrict__ ea, const float* __restrict__ nf,
      const int*   __restrict__ eidx,
      const float* __restrict__ W1, const float* __restrict__ b1,
      const float* __restrict__ gamma, const float* __restrict__ beta,
      const float* __restrict__ W2, const float* __restrict__ b2,
      const float* __restrict__ Wv, const float* __restrict__ bv,
      const float* __restrict__ Wo, const float* __restrict__ bo,
      const float* __restrict__ Wp, const float* __restrict__ bp,
      float* __restrict__ out)
{
    // s_buf: phase1 buf0 (16KB of it) / block0 chain (2x2304 floats = 18KB)
    __shared__ __align__(16) unsigned char s_buf[18432];
    __shared__ __align__(16) float tile2[4096];     // phase1 buf1 (16KB)
    __shared__ __align__(16) float2 w1frag[1024];   // GEMM1 B frags = tf32(0.5*W1)
    __shared__ __align__(16) float2 mfrag[1024];    // GEMM2 B frags (tau-permuted)
    __shared__ float2 b1frag[128];                  // b1 col pairs
    __shared__ float dhf[8];
    __shared__ float a_s[H_DIM], c_s[H_DIM];

    const int t = threadIdx.x;
    const int b = blockIdx.x;
    const int lane = t & 31, warp = t >> 5;
    const int g = lane >> 2, q4 = lane & 3;

    // ---- W1 (0.5-folded) / b1 fragment tables ----
    for (int i = t; i < 1024; i += 256) {
        int q = i >> 5, l = i & 31;
        int kk = l & 3, nn = l >> 2;
        float w0 = 0.5f * W1[kk * H_DIM + q * 8 + nn];
        float w1v = 0.5f * W1[(kk + 4) * H_DIM + q * 8 + nn];
        w1frag[i] = make_float2(__uint_as_float(tf32r(w0)), __uint_as_float(tf32r(w1v)));
    }
    for (int i = t; i < 128; i += 256) {
        int q = i >> 2, qq = i & 3;
        b1frag[i] = make_float2(b1[q * 8 + 2 * qq], b1[q * 8 + 2 * qq + 1]);
    }
    __syncthreads();

    if (b == 0) {
        // ============ weight chain (overlaps the stats pass) ============
        float* bufA = (float*)s_buf;
        float* bufB = bufA + 2304;
        for (int i = t; i < H_DIM * 8; i += 256)
            bufA[(i >> 3) * 9 + (i & 7)] = Wp[i];
        __syncthreads();
        float biask = 0.f;
        for (int j = lane; j < H_DIM; j += 32) biask += bo[j] * bufA[j * 9 + warp];
        for (int jj = warp; jj < H_DIM; jj += 8) {
            float a0=0,a1=0,a2=0,a3=0,a4=0,a5=0,a6=0,a7=0;
            #pragma unroll
            for (int qb = 0; qb < 8; qb++) {
                int q = qb * 32 + lane;
                float av = Wo[jj * H_DIM + q];
                const float* ir = bufA + q * 9;
                a0 += av*ir[0]; a1 += av*ir[1]; a2 += av*ir[2]; a3 += av*ir[3];
                a4 += av*ir[4]; a5 += av*ir[5]; a6 += av*ir[6]; a7 += av*ir[7];
            }
            a0=wred(a0); a1=wred(a1); a2=wred(a2); a3=wred(a3);
            a4=wred(a4); a5=wred(a5); a6=wred(a6); a7=wred(a7);
            if (lane == 0) {
                float* orow = bufB + jj * 9;
                orow[0]=a0; orow[1]=a1; orow[2]=a2; orow[3]=a3;
                orow[4]=a4; orow[5]=a5; orow[6]=a6; orow[7]=a7;
            }
        }
        __syncthreads();
        for (int j = lane; j < H_DIM; j += 32) biask += bv[j] * bufB[j * 9 + warp];
        for (int jj = warp; jj < H_DIM; jj += 8) {
            float a0=0,a1=0,a2=0,a3=0,a4=0,a5=0,a6=0,a7=0;
            #pragma unroll
            for (int qb = 0; qb < 8; qb++) {
                int q = qb * 32 + lane;
                float av = Wv[jj * H_DIM + q];
                const float* ir = bufB + q * 9;
                a0 += av*ir[0]; a1 += av*ir[1]; a2 += av*ir[2]; a3 += av*ir[3];
                a4 += av*ir[4]; a5 += av*ir[5]; a6 += av*ir[6]; a7 += av*ir[7];
            }
            a0=wred(a0); a1=wred(a1); a2=wred(a2); a3=wred(a3);
            a4=wred(a4); a5=wred(a5); a6=wred(a6); a7=wred(a7);
            if (lane == 0) {
                float* orow = bufA + jj * 9;
                orow[0]=a0; orow[1]=a1; orow[2]=a2; orow[3]=a3;
                orow[4]=a4; orow[5]=a5; orow[6]=a6; orow[7]=a7;
            }
        }
        __syncthreads();
        for (int j = lane; j < H_DIM; j += 32) biask += b2[j] * bufA[j * 9 + warp];
        for (int jj = warp; jj < H_DIM; jj += 8) {
            float a0=0,a1=0,a2=0,a3=0,a4=0,a5=0,a6=0,a7=0;
            #pragma unroll
            for (int qb = 0; qb < 8; qb++) {
                int q = qb * 32 + lane;
                float av = W2[jj * H_DIM + q];
                const float* ir = bufA + q * 9;
                a0 += av*ir[0]; a1 += av*ir[1]; a2 += av*ir[2]; a3 += av*ir[3];
                a4 += av*ir[4]; a5 += av*ir[5]; a6 += av*ir[6]; a7 += av*ir[7];
            }
            a0=wred(a0); a1=wred(a1); a2=wred(a2); a3=wred(a3);
            a4=wred(a4); a5=wred(a5); a6=wred(a6); a7=wred(a7);
            if (lane == 0) {
                float* orow = g_Craw + jj * 8;
                orow[0]=a0; orow[1]=a1; orow[2]=a2; orow[3]=a3;
                orow[4]=a4; orow[5]=a5; orow[6]=a6; orow[7]=a7;
            }
        }
        biask = wred(biask);
        if (lane == 0) g_biaspart[warp] = biask + bp[warp];
    } else {
        // ===== phase 1: double-buffered gather + tensor relu stats (f32x2 acc) =====
        int s1 = (b - 1) * PER1;
        int e1 = s1 + PER1; if (e1 > PAIRS) e1 = PAIRS;
        const float4* nf4 = (const float4*)nf;
        float* bufs[2] = { (float*)s_buf, tile2 };
        const int nt = (e1 - s1 + 255) >> 8;

        float2 wv0 = w1frag[((warp +  0) << 5) | lane];
        float2 wv1 = w1frag[((warp +  8) << 5) | lane];
        float2 wv2 = w1frag[((warp + 16) << 5) | lane];
        float2 wv3 = w1frag[((warp + 24) << 5) | lane];
        float2 bp0 = b1frag[((warp +  0) << 2) | q4];
        float2 bp1 = b1frag[((warp +  8) << 2) | q4];
        float2 bp2 = b1frag[((warp + 16) << 2) | q4];
        float2 bp3 = b1frag[((warp + 24) << 2) | q4];

        u64 ss01[4] = {0ull,0ull,0ull,0ull};
        u64 qq01[4] = {0ull,0ull,0ull,0ull};

        gather_tile(s1, e1, bufs[0], t, eidx, nf4);
        __syncthreads();

        for (int it = 0; it < nt; it++) {
            if (it + 1 < nt)
                gather_tile(s1 + (it + 1) * 256, e1, bufs[(it + 1) & 1], t, eidx, nf4);

            const float* tile = bufs[it & 1];
            #pragma unroll 4
            for (int et = 0; et < 32; et++) {
                int r0 = et * 16 + g;
                unsigned a0 = __float_as_uint(tile[r0 * 8 + q4]);
                unsigned a1 = __float_as_uint(tile[(r0 + 8) * 8 + q4]);
                unsigned a2 = __float_as_uint(tile[r0 * 8 + q4 + 4]);
                unsigned a3 = __float_as_uint(tile[(r0 + 8) * 8 + q4 + 4]);
                float h0, h1, h2, h3;
                u64 P01, P23;
                mma_init(h0, h1, h2, h3, a0, a1, a2, a3,
                         __float_as_uint(wv0.x), __float_as_uint(wv0.y),
                         bp0.x, bp0.y, bp0.x, bp0.y);
                P01 = pack2(fmaxf(h0, 0.f), fmaxf(h1, 0.f));
                P23 = pack2(fmaxf(h2, 0.f), fmaxf(h3, 0.f));
                ss01[0] = add2(ss01[0], P01); ss01[0] = add2(ss01[0], P23);
                qq01[0] = fma2(P01, P01, qq01[0]); qq01[0] = fma2(P23, P23, qq01[0]);
                mma_init(h0, h1, h2, h3, a0, a1, a2, a3,
                         __float_as_uint(wv1.x), __float_as_uint(wv1.y),
                         bp1.x, bp1.y, bp1.x, bp1.y);
                P01 = pack2(fmaxf(h0, 0.f), fmaxf(h1, 0.f));
                P23 = pack2(fmaxf(h2, 0.f), fmaxf(h3, 0.f));
                ss01[1] = add2(ss01[1], P01); ss01[1] = add2(ss01[1], P23);
                qq01[1] = fma2(P01, P01, qq01[1]); qq01[1] = fma2(P23, P23, qq01[1]);
                mma_init(h0, h1, h2, h3, a0, a1, a2, a3,
                         __float_as_uint(wv2.x), __float_as_uint(wv2.y),
                         bp2.x, bp2.y, bp2.x, bp2.y);
                P01 = pack2(fmaxf(h0, 0.f), fmaxf(h1, 0.f));
                P23 = pack2(fmaxf(h2, 0.f), fmaxf(h3, 0.f));
                ss01[2] = add2(ss01[2], P01); ss01[2] = add2(ss01[2], P23);
                qq01[2] = fma2(P01, P01, qq01[2]); qq01[2] = fma2(P23, P23, qq01[2]);
                mma_init(h0, h1, h2, h3, a0, a1, a2, a3,
                         __float_as_uint(wv3.x), __float_as_uint(wv3.y),
                         bp3.x, bp3.y, bp3.x, bp3.y);
                P01 = pack2(fmaxf(h0, 0.f), fmaxf(h1, 0.f));
                P23 = pack2(fmaxf(h2, 0.f), fmaxf(h3, 0.f));
                ss01[3] = add2(ss01[3], P01); ss01[3] = add2(ss01[3], P23);
                qq01[3] = fma2(P01, P01, qq01[3]); qq01[3] = fma2(P23, P23, qq01[3]);
            }
            __syncthreads();
        }

        // unpack, reduce over g lanes (xor 4, 8, 16), commit
        #pragma unroll
        for (int i = 0; i < 4; i++) {
            float ss0, ss1, qv0, qv1;
            unpack2(ss01[i], ss0, ss1);
            unpack2(qq01[i], qv0, qv1);
            #pragma unroll
            for (int off = 4; off <= 16; off <<= 1) {
                ss0 += __shfl_xor_sync(0xffffffffu, ss0, off);
                ss1 += __shfl_xor_sync(0xffffffffu, ss1, off);
                qv0 += __shfl_xor_sync(0xffffffffu, qv0, off);
                qv1 += __shfl_xor_sync(0xffffffffu, qv1, off);
            }
            if (lane < 4) {
                int q = warp + 8 * i;
                int col = q * 8 + 2 * q4;
                atomicAdd(&g_sum[col],     ss0);
                atomicAdd(&g_sum[col + 1], ss1);
                atomicAdd(&g_sumsq[col],     qv0);
                atomicAdd(&g_sumsq[col + 1], qv1);
            }
        }
    }

    // ============ grid barrier ============
    __syncthreads();
    if (t == 0) {
        __threadfence();
        if (atomicAdd(&g_arrive, 1) == GRID - 1) {
            g_release = 1;
        } else {
            while (g_release == 0) { }
        }
        __threadfence();
    }
    __syncthreads();

    // ============ finalize BN (fake-row corrected), dh, mfrag ============
    {
        const float invE = 1.f / (float)E_NUM;
        float rb = fmaxf(b1[t], 0.f);
        float sum   = g_sum[t]   - (float)NFAKE * rb;
        float sumsq = g_sumsq[t] - (float)NFAKE * rb * rb;
        float mu  = sum * invE;
        float var = sumsq * invE - mu * mu;
        float aj  = gamma[t] * rsqrtf(var + BN_EPS);
        a_s[t] = aj;
        c_s[t] = beta[t] - mu * aj;
    }
    __syncthreads();
    {
        float acc = 0.f;
        for (int j = lane; j < H_DIM; j += 32) acc += c_s[j] * g_Craw[j * 8 + warp];
        acc = wred(acc);
        if (lane == 0) dhf[warp] = 0.5f * (acc + g_biaspart[warp]);
    }
    for (int i = t; i < 1024; i += 256) {
        int q = i >> 5, l = i & 31;
        int kk = l & 3, nn = l >> 2;
        // GEMM2 B rows tau-permuted: slot kk -> j = q*8+2kk; slot kk+4 -> j = q*8+2kk+1
        int j0 = q * 8 + 2 * kk;
        float m0 = 0.5f * a_s[j0] * g_Craw[j0 * 8 + nn];
        float m1 = 0.5f * a_s[j0 + 1] * g_Craw[(j0 + 1) * 8 + nn];
        mfrag[i] = make_float2(__uint_as_float(tf32r(m0)), __uint_as_float(tf32r(m1)));
    }
    __syncthreads();

    // ============ phase 2: tensor contraction, 2 tiles/warp interleaved ======
    {
        const int warp_gid = b * 8 + warp;
        const float dh0 = dhf[2 * q4], dh1 = dhf[2 * q4 + 1];

        int tau = warp_gid;
        for (; tau + NWARPS < NTILES; tau += 2 * NWARPS) {
            int peX = tau << 4;
            int peY = (tau + NWARPS) << 4;
            const float* rX0 = g_ncf + (size_t)(peX + g) * 8;
            const float* rY0 = g_ncf + (size_t)(peY + g) * 8;
            unsigned aX0 = __float_as_uint(rX0[q4]);
            unsigned aX1 = __float_as_uint(rX0[64 + q4]);
            unsigned aX2 = __float_as_uint(rX0[q4 + 4]);
            unsigned aX3 = __float_as_uint(rX0[64 + q4 + 4]);
            unsigned aY0 = __float_as_uint(rY0[q4]);
            unsigned aY1 = __float_as_uint(rY0[64 + q4]);
            unsigned aY2 = __float_as_uint(rY0[q4 + 4]);
            unsigned aY3 = __float_as_uint(rY0[64 + q4 + 4]);
            float cX0 = dh0, cX1 = dh1, cX2 = dh0, cX3 = dh1;
            float cY0 = dh0, cY1 = dh1, cY2 = dh0, cY3 = dh1;

            #pragma unroll 4
            for (int q = 0; q < 32; q++) {
                float2 bpv = b1frag[(q << 2) | q4];
                float2 wv = w1frag[(q << 5) | lane];
                float2 mv = mfrag[(q << 5) | lane];
                unsigned wb0 = __float_as_uint(wv.x), wb1 = __float_as_uint(wv.y);
                unsigned mb0 = __float_as_uint(mv.x), mb1 = __float_as_uint(mv.y);
                float hX0, hX1, hX2, hX3, hY0, hY1, hY2, hY3;
                mma_init(hX0, hX1, hX2, hX3, aX0, aX1, aX2, aX3, wb0, wb1,
                         bpv.x, bpv.y, bpv.x, bpv.y);
                mma_init(hY0, hY1, hY2, hY3, aY0, aY1, aY2, aY3, wb0, wb1,
                         bpv.x, bpv.y, bpv.x, bpv.y);
                unsigned xX0 = __float_as_uint(fmaxf(hX0, 0.f));
                unsigned xX1 = __float_as_uint(fmaxf(hX2, 0.f));
                unsigned xX2 = __float_as_uint(fmaxf(hX1, 0.f));
                unsigned xX3 = __float_as_uint(fmaxf(hX3, 0.f));
                unsigned xY0 = __float_as_uint(fmaxf(hY0, 0.f));
                unsigned xY1 = __float_as_uint(fmaxf(hY2, 0.f));
                unsigned xY2 = __float_as_uint(fmaxf(hY1, 0.f));
                unsigned xY3 = __float_as_uint(fmaxf(hY3, 0.f));
                mma_acc(cX0, cX1, cX2, cX3, xX0, xX1, xX2, xX3, mb0, mb1);
                mma_acc(cY0, cY1, cY2, cY3, xY0, xY1, xY2, xY3, mb0, mb1);
            }

            size_t oX = (size_t)(peX + g) * 8 + 2 * q4;
            size_t oY = (size_t)(peY + g) * 8 + 2 * q4;
            float2 eX1 = *(const float2*)(ea + oX);
            float2 eX2 = *(const float2*)(ea + oX + 64);
            float2 eY1 = *(const float2*)(ea + oY);
            float2 eY2 = *(const float2*)(ea + oY + 64);
            *(float2*)(out + oX)      = make_float2(eX1.x + cX0, eX1.y + cX1);
            *(float2*)(out + oX + 64) = make_float2(eX2.x + cX2, eX2.y + cX3);
            *(float2*)(out + oY)      = make_float2(eY1.x + cY0, eY1.y + cY1);
            *(float2*)(out + oY + 64) = make_float2(eY2.x + cY2, eY2.y + cY3);
        }
        if (tau < NTILES) {
            int pe = tau << 4;
            const float* r0 = g_ncf + (size_t)(pe + g) * 8;
            unsigned a0 = __float_as_uint(r0[q4]);
            unsigned a1 = __float_as_uint(r0[64 + q4]);
            unsigned a2 = __float_as_uint(r0[q4 + 4]);
            unsigned a3 = __float_as_uint(r0[64 + q4 + 4]);
            float c0 = dh0, c1 = dh1, c2 = dh0, c3 = dh1;
            #pragma unroll 4
            for (int q = 0; q < 32; q++) {
                float2 bpv = b1frag[(q << 2) | q4];
                float2 wv = w1frag[(q << 5) | lane];
                float2 mv = mfrag[(q << 5) | lane];
                float h0, h1, h2, h3;
                mma_init(h0, h1, h2, h3, a0, a1, a2, a3,
                         __float_as_uint(wv.x), __float_as_uint(wv.y),
                         bpv.x, bpv.y, bpv.x, bpv.y);
                unsigned x0 = __float_as_uint(fmaxf(h0, 0.f));
                unsigned x1 = __float_as_uint(fmaxf(h2, 0.f));
                unsigned x2 = __float_as_uint(fmaxf(h1, 0.f));
                unsigned x3 = __float_as_uint(fmaxf(h3, 0.f));
                mma_acc(c0, c1, c2, c3, x0, x1, x2, x3,
                        __float_as_uint(mv.x), __float_as_uint(mv.y));
            }
            size_t o1 = (size_t)(pe + g) * 8 + 2 * q4;
            float2 e1 = *(const float2*)(ea + o1);
            float2 e2v = *(const float2*)(ea + o1 + 64);
            *(float2*)(out + o1)      = make_float2(e1.x + c0, e1.y + c1);
            *(float2*)(out + o1 + 64) = make_float2(e2v.x + c2, e2v.y + c3);
        }
    }

    // ============ reset (last finisher) ============
    __syncthreads();
    if (t == 0) {
        __threadfence();
        if (atomicAdd(&g_finish, 1) == GRID - 1) {
            g_arrive = 0;
            g_release = 0;
            for (int i = 0; i < H_DIM; i++) { g_sum[i] = 0.f; g_sumsq[i] = 0.f; }
            __threadfence();
            g_finish = 0;
        }
    }
}

// -------- launch --------
extern "C" void kernel_launch(void* const* d_in, const int* in_sizes, int n_in,
                              void* d_out, int out_size) {
    (void)in_sizes; (void)n_in; (void)out_size;
    const float* edge_attr = (const float*)d_in[0];
    const float* nf        = (const float*)d_in[1];
    const int*   eidx      = (const int*)d_in[2];
    // d_in[3..8] = edge-encoder weights: dead code in the reference
    const float* W1    = (const float*)d_in[9];
    const float* b1    = (const float*)d_in[10];
    const float* gamma = (const float*)d_in[11];
    const float* beta  = (const float*)d_in[12];
    const float* W2    = (const float*)d_in[13];
    const float* b2    = (const float*)d_in[14];
    const float* Wv    = (const float*)d_in[15];
    const float* bv    = (const float*)d_in[16];
    const float* Wo    = (const float*)d_in[17];
    const float* bo    = (const float*)d_in[18];
    const float* Wp    = (const float*)d_in[19];
    const float* bp    = (const float*)d_in[20];
    float* out = (float*)d_out;

    fused<<<GRID, 256>>>(edge_attr, nf, eidx, W1, b1, gamma, beta,
                         W2, b2, Wv, bv, Wo, bo, Wp, bp, out);
}